// round 16
// baseline (speedup 1.0000x reference)
#include <cuda_runtime.h>
#include <cuda_fp16.h>
#include <cstdint>
#include <cstddef>

// ============================================================
// Problem constants
// ============================================================
constexpr int N_ACT = 200000;
constexpr int CDIM  = 128;
constexpr int KOFF  = 27;
constexpr float BN_EPS = 1e-4f;

constexpr int BM           = 256;                       // output rows per CTA
constexpr int NBLK         = (N_ACT + BM - 1) / BM;     // 782
constexpr int CONV_THREADS = 512;                       // 16 warps

// SMEM layout (dynamic); A/B tiles use 256B-stride XOR swizzle
constexpr uint32_t OFF_ACC   = 0;                       // 256 x 128 fp32, rotated pairs
constexpr uint32_t ACC_B     = 256u * 512u;             // 131072
constexpr uint32_t OFF_A     = OFF_ACC + ACC_B;         // 131072 ; 2 x 64x256
constexpr uint32_t A_TILE    = 64u * 256u;              // 16384
constexpr uint32_t OFF_B     = OFF_A + 2u * A_TILE;     // 163840 ; 2 x 128x256
constexpr uint32_t B_TILE    = 128u * 256u;             // 32768
constexpr uint32_t OFF_STRIP = OFF_B + 2u * B_TILE;     // 229376 ; 2 x 64 ints
constexpr uint32_t OFF_CNT   = OFF_STRIP + 512;         // 229888 ; 27 ints (pad 112)
constexpr uint32_t OFF_WORK  = OFF_CNT + 112;           // 230000 ; up to 108 ints
constexpr uint32_t OFF_NW    = OFF_WORK + 448;          // 230448
constexpr uint32_t SMEM_TOTAL = OFF_NW + 16;            // 230464  (< 232448 limit)

// ============================================================
// Device scratch
// ============================================================
__device__ __align__(16) __half g_Af16[(size_t)N_ACT * CDIM];          // 51.2 MB
__device__ __align__(16) __half g_Cf16[(size_t)N_ACT * CDIM];          // 51.2 MB conv out (fp16)
__device__ __align__(16) __half g_Wt16[(size_t)KOFF * CDIM * CDIM];    // [k][cout][cin]
__device__ int g_cidx[(size_t)NBLK * KOFF * BM];        // compact rulebook (idx | row<<18)
__device__ int g_cnt [NBLK * KOFF];
__device__ float g_psum[NBLK * CDIM];
__device__ float g_psq [NBLK * CDIM];
__device__ __align__(16) float g_scale[CDIM];
__device__ __align__(16) float g_bias [CDIM];

// ============================================================
// Helpers
// ============================================================
__device__ __forceinline__ uint32_t smem_u32(const void* p) {
    uint32_t a;
    asm("{ .reg .u64 t; cvta.to.shared.u64 t, %1; cvt.u32.u64 %0, t; }" : "=r"(a) : "l"(p));
    return a;
}
__device__ __forceinline__ void cp_async16(uint32_t dst, const void* src) {
    asm volatile("cp.async.cg.shared.global [%0], [%1], 16;" :: "r"(dst), "l"(src) : "memory");
}
__device__ __forceinline__ void sts_fill16(uint32_t dst, uint32_t v) {
    asm volatile("st.shared.v4.b32 [%0], {%1, %1, %1, %1};" :: "r"(dst), "r"(v) : "memory");
}
__device__ __forceinline__ void cp_commit() {
    asm volatile("cp.async.commit_group;" ::: "memory");
}
template <int N>
__device__ __forceinline__ void cp_wait() {
    asm volatile("cp.async.wait_group %0;" :: "n"(N) : "memory");
}
__device__ __forceinline__ void ldsm_x4(uint32_t* r, uint32_t addr) {
    asm volatile("ldmatrix.sync.aligned.m8n8.x4.shared.b16 {%0,%1,%2,%3}, [%4];"
                 : "=r"(r[0]), "=r"(r[1]), "=r"(r[2]), "=r"(r[3]) : "r"(addr));
}
__device__ __forceinline__ void mma16816(float* d, const uint32_t* a, const uint32_t* b) {
    asm volatile(
        "mma.sync.aligned.m16n8k16.row.col.f32.f16.f16.f32 "
        "{%0,%1,%2,%3}, {%4,%5,%6,%7}, {%8,%9}, {%0,%1,%2,%3};"
        : "+f"(d[0]), "+f"(d[1]), "+f"(d[2]), "+f"(d[3])
        : "r"(a[0]), "r"(a[1]), "r"(a[2]), "r"(a[3]), "r"(b[0]), "r"(b[1]));
}
// 256B-stride tile swizzle: 16B chunk c (0..15), XOR low3 with row&7.
__device__ __forceinline__ uint32_t swz(int row, int c) {
    return (uint32_t)row * 256u + 16u * (uint32_t)((c & 8) | ((c & 7) ^ (row & 7)));
}
// Accumulator: row r (0..255), pair pp (0..63), rotated across banks.
__device__ __forceinline__ uint32_t acc_off(int r, int pp) {
    return OFF_ACC + (uint32_t)r * 512u + (uint32_t)(((pp + r * 8) & 63) << 3);
}

// ============================================================
// Kernel 1a: features fp32 -> fp16 (2 x float4 per thread)
// ============================================================
__global__ void cvt_features_kernel(const float* __restrict__ f) {
    size_t i0 = 2 * ((size_t)blockIdx.x * blockDim.x + threadIdx.x);
    #pragma unroll
    for (int j = 0; j < 2; j++) {
        size_t idx = i0 + j;
        if (idx < (size_t)N_ACT * CDIM / 4) {
            float4 v = reinterpret_cast<const float4*>(f)[idx];
            __half2* dst = reinterpret_cast<__half2*>(g_Af16) + 2 * idx;
            dst[0] = __floats2half2_rn(v.x, v.y);
            dst[1] = __floats2half2_rn(v.z, v.w);
        }
    }
}

// ============================================================
// Kernel 1b: W [k][cin][cout] fp32 -> Wt [k][cout][cin] fp16
// ============================================================
__global__ void cvt_w_kernel(const float* __restrict__ W) {
    int m = blockIdx.x * blockDim.x + threadIdx.x;
    int k   = m >> 14;
    int rem = m & 16383;
    int c   = rem >> 7;   // cout
    int j   = rem & 127;  // cin
    g_Wt16[m] = __float2half_rn(W[(k << 14) + (j << 7) + c]);
}

// ============================================================
// Kernel 1c: build global compact rulebook, one block per (row-block, k)
// ============================================================
__global__ void compact_kernel(const int* __restrict__ nbr) {
    const int b = blockIdx.x;
    const int k = blockIdx.y;
    const int t = threadIdx.x;       // 256 threads
    const int lid = t & 31;
    const int w = t >> 5;            // 8 warps
    __shared__ int wcnt[8];

    int r = b * BM + t;
    int idx = (r < N_ACT) ? nbr[(size_t)k * N_ACT + r] : -1;
    bool valid = (idx >= 0);
    unsigned bal = __ballot_sync(0xFFFFFFFFu, valid);
    if (lid == 0) wcnt[w] = __popc(bal);
    __syncthreads();
    int base = 0;
    #pragma unroll
    for (int j = 0; j < 8; j++) base += (j < w) ? wcnt[j] : 0;
    int pos = base + __popc(bal & ((1u << lid) - 1u));
    if (valid) g_cidx[((size_t)b * KOFF + k) * BM + pos] = idx | (t << 18);
    if (t == 0) {
        int tot = 0;
        #pragma unroll
        for (int j = 0; j < 8; j++) tot += wcnt[j];
        g_cnt[b * KOFF + k] = tot;
    }
}

// ============================================================
// Kernel 2: compacted sparse conv; double-buffered A+B, one barrier/unit,
//           warp-uniform skip of empty half-subtiles
// ============================================================
__global__ void __launch_bounds__(CONV_THREADS, 1)
conv_kernel() {
    extern __shared__ char smem[];
    const uint32_t sb = smem_u32(smem);
    const int tid = threadIdx.x;
    const int wid = tid >> 5;
    const int lid = tid & 31;
    const int b = blockIdx.x;
    const int row0 = b * BM;

    int* s_strip = reinterpret_cast<int*>(smem + OFF_STRIP);   // [2][64]
    int* s_cnt   = reinterpret_cast<int*>(smem + OFF_CNT);
    int* s_work  = reinterpret_cast<int*>(smem + OFF_WORK);
    int* s_nw    = reinterpret_cast<int*>(smem + OFF_NW);

    // ---- zero the smem accumulator (32768 floats) + fetch cnts ----
    {
        float4* a4 = reinterpret_cast<float4*>(smem + OFF_ACC);
        #pragma unroll
        for (int i = 0; i < 16; i++)
            a4[tid + i * CONV_THREADS] = make_float4(0.f, 0.f, 0.f, 0.f);
    }
    if (tid < KOFF) s_cnt[tid] = g_cnt[b * KOFF + tid];
    __syncthreads();
    // worklist entry: (k<<3) | (s<<1) | last_unit_of_k
    if (tid == 0) {
        int nw = 0;
        for (int k = 0; k < KOFF; k++) {
            int ns = (s_cnt[k] + 63) >> 6;
            for (int s = 0; s < ns; s++)
                s_work[nw++] = (k << 3) | (s << 1) | ((s == ns - 1) ? 1 : 0);
        }
        *s_nw = nw;
    }
    __syncthreads();
    const int nwork = *s_nw;

    // ---- tile loaders ----
    auto load_A = [&](int w, int buf) {
        int e = s_work[w];
        int k = e >> 3, s = (e >> 1) & 3;
        int cnt = s_cnt[k];
        int p = tid >> 3;
        int o = tid & 7;
        uint32_t dst0 = sb + OFF_A + (uint32_t)buf * A_TILE + swz(p, o);
        uint32_t dst1 = sb + OFF_A + (uint32_t)buf * A_TILE + swz(p, o + 8);
        int pos = s * 64 + p;
        if (pos < cnt) {
            int ent = __ldg(&g_cidx[((size_t)b * KOFF + k) * BM + pos]);
            if (o == 0) s_strip[buf * 64 + p] = ent;
            const char* src = (const char*)g_Af16 + (size_t)((uint32_t)ent & 0x3FFFFu) * 256 + o * 16;
            cp_async16(dst0, src);
            cp_async16(dst1, src + 128);
        } else if (p < 32 || s * 64 + 32 < cnt) {
            // zero-fill only rows the GEMM will actually read
            // (upper half skipped entirely when s*64+32 >= cnt)
            sts_fill16(dst0, 0u);
            sts_fill16(dst1, 0u);
        }
    };
    auto load_B = [&](int k, int buf) {
        int n = tid >> 2;
        int qq = tid & 3;
        const char* src = (const char*)g_Wt16 + ((size_t)k * 128 + n) * 256;
        uint32_t base = sb + OFF_B + (uint32_t)buf * B_TILE;
        #pragma unroll
        for (int j = 0; j < 4; j++) {
            int c = qq * 4 + j;
            cp_async16(base + swz(n, c), src + c * 16);
        }
    };

    // ---- per-lane fragment pieces (16 warps: 2M x 8N, warp tile 32x16) ----
    const int mg = wid & 1;
    const int ng = wid >> 1;
    const int a_r0 = mg * 32 + (lid & 15);
    const int a_cs = lid >> 4;                 // A chunk parity
    const int b_r  = ng * 16 + (lid & 7) + ((lid & 16) ? 8 : 0);
    const int b_cs = (lid >> 3) & 1;           // B chunk parity
    const int p_base  = mg * 32 + (lid >> 2);  // compact slot base
    const int pp_base = ng * 8 + (lid & 3);    // acc pair base

    // ---- prime: B(k0) buf0, A(unit 0) buf0 ----
    load_B(s_work[0] >> 3, 0);
    load_A(0, 0);
    cp_commit();
    int bbuf = 0;

    #pragma unroll 1
    for (int w = 0; w < nwork; w++) {
        const int e = s_work[w];
        const int k = e >> 3, s = (e >> 1) & 3;
        const bool last = (e & 1) != 0;
        const int abuf = w & 1;
        const int cnt = s_cnt[k];

        cp_wait<0>();      // A(w) [+B group if pending] complete
        __syncthreads();   // S1: all warps done GEMM(w-1)+scatter(w-1); tiles visible

        // issue next loads (covered by this unit's GEMM + scatter)
        if (w + 1 < nwork) {
            load_A(w + 1, abuf ^ 1);
            if (last) load_B(s_work[w + 1] >> 3, bbuf ^ 1);
            cp_commit();
        }

        // ---- 64x128x128 compact GEMM (warp tile 32x16);
        //      warp-uniform skip when this warp's 32-row half has no valid rows ----
        float facc[2][2][4];
        #pragma unroll
        for (int a = 0; a < 2; a++)
            #pragma unroll
            for (int b2 = 0; b2 < 2; b2++)
                #pragma unroll
                for (int c = 0; c < 4; c++) facc[a][b2][c] = 0.f;
        if (s * 64 + mg * 32 < cnt) {
            const uint32_t ab  = sb + OFF_A + (uint32_t)abuf * A_TILE;
            const uint32_t bbs = sb + OFF_B + (uint32_t)bbuf * B_TILE;
            #pragma unroll
            for (int ks = 0; ks < 8; ks++) {
                uint32_t af0[4], af1[4], t[4];
                int ca = ks * 2 + a_cs;
                int cb = ks * 2 + b_cs;
                ldsm_x4(af0, ab + swz(a_r0, ca));
                ldsm_x4(af1, ab + swz(a_r0 + 16, ca));
                ldsm_x4(t, bbs + swz(b_r, cb));
                uint32_t bf0[2] = {t[0], t[1]};
                uint32_t bf1[2] = {t[2], t[3]};
                mma16816(facc[0][0], af0, bf0);
                mma16816(facc[0][1], af0, bf1);
                mma16816(facc[1][0], af1, bf0);
                mma16816(facc[1][1], af1, bf1);
            }
        }

        // ---- direct scatter-add into smem accumulator (strip-cached rows) ----
        {
            const int base_s = s * 64;
            #pragma unroll
            for (int mf = 0; mf < 2; mf++)
                #pragma unroll
                for (int h = 0; h < 2; h++) {
                    int slot = p_base + mf * 16 + h * 8;
                    if (base_s + slot < cnt) {
                        int r = ((uint32_t)s_strip[abuf * 64 + slot]) >> 18;
                        #pragma unroll
                        for (int nf = 0; nf < 2; nf++) {
                            uint32_t ad = acc_off(r, pp_base + nf * 4);
                            float2 v = *reinterpret_cast<float2*>(smem + ad);
                            v.x += facc[mf][nf][2 * h];
                            v.y += facc[mf][nf][2 * h + 1];
                            *reinterpret_cast<float2*>(smem + ad) = v;
                        }
                    }
                }
        }
        if (last) bbuf ^= 1;
    }
    __syncthreads();   // final scatter complete

    // ---- epilogue: smem acc -> fp16 intermediate, + BN partials (fp32 stats) ----
    {
        const int pp = tid & 63;     // pair (2 channels)
        const int g  = tid >> 6;     // row group 0..7 (32 rows each)
        float s0 = 0.f, s1 = 0.f, q0 = 0.f, q1 = 0.f;
        #pragma unroll 4
        for (int rr = 0; rr < 32; rr++) {
            int r = g * 32 + rr;
            float2 v = *reinterpret_cast<float2*>(smem + acc_off(r, pp));
            int row = row0 + r;
            if (row < N_ACT)
                reinterpret_cast<__half2*>(g_Cf16)[(size_t)row * 64 + pp] =
                    __floats2half2_rn(v.x, v.y);
            s0 += v.x; s1 += v.y;
            q0 = fmaf(v.x, v.x, q0);
            q1 = fmaf(v.y, v.y, q1);
        }
        __syncthreads();
        float4* red = reinterpret_cast<float4*>(smem + OFF_A);   // [8][64]
        red[g * 64 + pp] = make_float4(s0, s1, q0, q1);
        __syncthreads();
        if (tid < 64) {
            float ts0 = 0.f, ts1 = 0.f, tq0 = 0.f, tq1 = 0.f;
            #pragma unroll
            for (int gg = 0; gg < 8; gg++) {
                float4 v = red[gg * 64 + tid];
                ts0 += v.x; ts1 += v.y; tq0 += v.z; tq1 += v.w;
            }
            g_psum[b * CDIM + tid * 2]     = ts0;
            g_psum[b * CDIM + tid * 2 + 1] = ts1;
            g_psq [b * CDIM + tid * 2]     = tq0;
            g_psq [b * CDIM + tid * 2 + 1] = tq1;
        }
    }
}

// ============================================================
// Kernel 3: finalize BN scale/bias (parallel, deterministic tree)
// ============================================================
__global__ void bn_final_kernel(const float* __restrict__ gamma, const float* __restrict__ beta) {
    __shared__ float ss[256], sq[256];
    int c = blockIdx.x;
    int t = threadIdx.x;
    float s = 0.f, q = 0.f;
    for (int b = t; b < NBLK; b += 256) {
        s += g_psum[b * CDIM + c];
        q += g_psq [b * CDIM + c];
    }
    ss[t] = s; sq[t] = q;
    __syncthreads();
    #pragma unroll
    for (int st = 128; st > 0; st >>= 1) {
        if (t < st) { ss[t] += ss[t + st]; sq[t] += sq[t + st]; }
        __syncthreads();
    }
    if (t == 0) {
        float mean = ss[0] / (float)N_ACT;
        float var  = sq[0] / (float)N_ACT - mean * mean;
        float sc   = gamma[c] * rsqrtf(var + BN_EPS);
        g_scale[c] = sc;
        g_bias[c]  = beta[c] - mean * sc;
    }
}

// ============================================================
// Kernel 4: apply BN + ReLU (reads fp16 intermediate, writes fp32 out)
// ============================================================
__global__ void bn_apply_kernel(float* __restrict__ out) {
    size_t i0 = 2 * ((size_t)blockIdx.x * blockDim.x + threadIdx.x);
    #pragma unroll
    for (int j = 0; j < 2; j++) {
        size_t idx = i0 + j;   // float4-chunk index (4 channels)
        if (idx < (size_t)N_ACT * CDIM / 4) {
            int c4 = (int)(idx & 31);
            uint2 u = reinterpret_cast<const uint2*>(g_Cf16)[idx];
            float2 v01 = __half22float2(*reinterpret_cast<__half2*>(&u.x));
            float2 v23 = __half22float2(*reinterpret_cast<__half2*>(&u.y));
            float4 sc = reinterpret_cast<float4*>(g_scale)[c4];
            float4 bi = reinterpret_cast<float4*>(g_bias)[c4];
            float4 v;
            v.x = fmaxf(fmaf(v01.x, sc.x, bi.x), 0.f);
            v.y = fmaxf(fmaf(v01.y, sc.y, bi.y), 0.f);
            v.z = fmaxf(fmaf(v23.x, sc.z, bi.z), 0.f);
            v.w = fmaxf(fmaf(v23.y, sc.w, bi.w), 0.f);
            reinterpret_cast<float4*>(out)[idx] = v;
        }
    }
}

// ============================================================
// Launch
// ============================================================
extern "C" void kernel_launch(void* const* d_in, const int* in_sizes, int n_in,
                              void* d_out, int out_size) {
    const float* features = (const float*)d_in[0];
    const int*   nbr      = (const int*)d_in[1];
    const float* W        = (const float*)d_in[2];
    const float* gamma    = (const float*)d_in[3];
    const float* beta     = (const float*)d_in[4];
    float* out = (float*)d_out;

    cudaFuncSetAttribute((const void*)conv_kernel,
                         cudaFuncAttributeMaxDynamicSharedMemorySize, SMEM_TOTAL);

    const int chunks = N_ACT * CDIM / 4;          // 6,400,000 float4
    cvt_features_kernel<<<(chunks / 2 + 255) / 256, 256>>>(features);
    cvt_w_kernel<<<KOFF * CDIM * CDIM / 256, 256>>>(W);
    compact_kernel<<<dim3(NBLK, KOFF), 256>>>(nbr);
    conv_kernel<<<NBLK, CONV_THREADS, SMEM_TOTAL>>>();      // launch #3 = ncu capture slot
    bn_final_kernel<<<CDIM, 256>>>(gamma, beta);
    bn_apply_kernel<<<(chunks / 2 + 255) / 256, 256>>>(out);
}

// round 17
// speedup vs baseline: 1.0236x; 1.0236x over previous
#include <cuda_runtime.h>
#include <cuda_fp16.h>
#include <cstdint>
#include <cstddef>

// ============================================================
// Problem constants
// ============================================================
constexpr int N_ACT = 200000;
constexpr int CDIM  = 128;
constexpr int KOFF  = 27;
constexpr float BN_EPS = 1e-4f;

constexpr int BM           = 256;                       // output rows per CTA
constexpr int NBLK         = (N_ACT + BM - 1) / BM;     // 782
constexpr int CONV_THREADS = 512;                       // 16 warps

// Fused prep kernel block ranges (256 threads each)
constexpr int CVTF_CHUNKS = N_ACT * CDIM / 4;           // 6,400,000 float4
constexpr int CVTF_BLK    = (CVTF_CHUNKS / 2 + 255) / 256;   // 12500
constexpr int CVTW_BLK    = KOFF * CDIM * CDIM / 256;        // 1728
constexpr int CMP_BLK     = NBLK * KOFF;                     // 21114
constexpr int PREP_BLK    = CVTF_BLK + CVTW_BLK + CMP_BLK;

// SMEM layout (dynamic); A/B tiles use 256B-stride XOR swizzle
constexpr uint32_t OFF_ACC   = 0;                       // 256 x 128 fp32, rotated pairs
constexpr uint32_t ACC_B     = 256u * 512u;             // 131072
constexpr uint32_t OFF_A     = OFF_ACC + ACC_B;         // 131072 ; 2 x 64x256
constexpr uint32_t A_TILE    = 64u * 256u;              // 16384
constexpr uint32_t OFF_B     = OFF_A + 2u * A_TILE;     // 163840 ; 2 x 128x256
constexpr uint32_t B_TILE    = 128u * 256u;             // 32768
constexpr uint32_t OFF_STRIP = OFF_B + 2u * B_TILE;     // 229376 ; 2 x 64 ints
constexpr uint32_t OFF_CNT   = OFF_STRIP + 512;         // 229888 ; 27 ints (pad 112)
constexpr uint32_t OFF_WORK  = OFF_CNT + 112;           // 230000 ; up to 108 ints
constexpr uint32_t OFF_NW    = OFF_WORK + 448;          // 230448
constexpr uint32_t SMEM_TOTAL = OFF_NW + 16;            // 230464  (< 232448 limit)

// ============================================================
// Device scratch
// ============================================================
__device__ __align__(16) __half g_Af16[(size_t)N_ACT * CDIM];          // 51.2 MB
__device__ __align__(16) __half g_Cf16[(size_t)N_ACT * CDIM];          // 51.2 MB conv out (fp16)
__device__ __align__(16) __half g_Wt16[(size_t)KOFF * CDIM * CDIM];    // [k][cout][cin]
__device__ int g_cidx[(size_t)NBLK * KOFF * BM];        // compact rulebook (idx | row<<18)
__device__ int g_cnt [NBLK * KOFF];
__device__ float g_psum[NBLK * CDIM];
__device__ float g_psq [NBLK * CDIM];
__device__ __align__(16) float g_scale[CDIM];
__device__ __align__(16) float g_bias [CDIM];

// ============================================================
// Helpers
// ============================================================
__device__ __forceinline__ uint32_t smem_u32(const void* p) {
    uint32_t a;
    asm("{ .reg .u64 t; cvta.to.shared.u64 t, %1; cvt.u32.u64 %0, t; }" : "=r"(a) : "l"(p));
    return a;
}
__device__ __forceinline__ void cp_async16(uint32_t dst, const void* src) {
    asm volatile("cp.async.cg.shared.global [%0], [%1], 16;" :: "r"(dst), "l"(src) : "memory");
}
__device__ __forceinline__ void sts_fill16(uint32_t dst, uint32_t v) {
    asm volatile("st.shared.v4.b32 [%0], {%1, %1, %1, %1};" :: "r"(dst), "r"(v) : "memory");
}
__device__ __forceinline__ void cp_commit() {
    asm volatile("cp.async.commit_group;" ::: "memory");
}
template <int N>
__device__ __forceinline__ void cp_wait() {
    asm volatile("cp.async.wait_group %0;" :: "n"(N) : "memory");
}
__device__ __forceinline__ void ldsm_x4(uint32_t* r, uint32_t addr) {
    asm volatile("ldmatrix.sync.aligned.m8n8.x4.shared.b16 {%0,%1,%2,%3}, [%4];"
                 : "=r"(r[0]), "=r"(r[1]), "=r"(r[2]), "=r"(r[3]) : "r"(addr));
}
__device__ __forceinline__ void mma16816(float* d, const uint32_t* a, const uint32_t* b) {
    asm volatile(
        "mma.sync.aligned.m16n8k16.row.col.f32.f16.f16.f32 "
        "{%0,%1,%2,%3}, {%4,%5,%6,%7}, {%8,%9}, {%0,%1,%2,%3};"
        : "+f"(d[0]), "+f"(d[1]), "+f"(d[2]), "+f"(d[3])
        : "r"(a[0]), "r"(a[1]), "r"(a[2]), "r"(a[3]), "r"(b[0]), "r"(b[1]));
}
// 256B-stride tile swizzle: 16B chunk c (0..15), XOR low3 with row&7.
__device__ __forceinline__ uint32_t swz(int row, int c) {
    return (uint32_t)row * 256u + 16u * (uint32_t)((c & 8) | ((c & 7) ^ (row & 7)));
}
// Accumulator: row r (0..255), pair pp (0..63), rotated across banks.
__device__ __forceinline__ uint32_t acc_off(int r, int pp) {
    return OFF_ACC + (uint32_t)r * 512u + (uint32_t)(((pp + r * 8) & 63) << 3);
}

// ============================================================
// Kernel 1: fused prep — cvt_features | cvt_w | compact by block range
// ============================================================
__global__ void __launch_bounds__(256)
prep_kernel(const float* __restrict__ features, const float* __restrict__ W,
            const int* __restrict__ nbr) {
    const int bid = blockIdx.x;
    if (bid < CVTF_BLK) {
        // ---- features fp32 -> fp16 (2 x float4 per thread) ----
        size_t i0 = 2 * ((size_t)bid * 256 + threadIdx.x);
        #pragma unroll
        for (int j = 0; j < 2; j++) {
            size_t idx = i0 + j;
            if (idx < (size_t)CVTF_CHUNKS) {
                float4 v = reinterpret_cast<const float4*>(features)[idx];
                __half2* dst = reinterpret_cast<__half2*>(g_Af16) + 2 * idx;
                dst[0] = __floats2half2_rn(v.x, v.y);
                dst[1] = __floats2half2_rn(v.z, v.w);
            }
        }
    } else if (bid < CVTF_BLK + CVTW_BLK) {
        // ---- W [k][cin][cout] fp32 -> Wt [k][cout][cin] fp16 ----
        int m = (bid - CVTF_BLK) * 256 + threadIdx.x;
        int k   = m >> 14;
        int rem = m & 16383;
        int c   = rem >> 7;   // cout
        int j   = rem & 127;  // cin
        g_Wt16[m] = __float2half_rn(W[(k << 14) + (j << 7) + c]);
    } else {
        // ---- compact rulebook: one block per (row-block b, offset k) ----
        int e = bid - CVTF_BLK - CVTW_BLK;
        const int b = e / KOFF;
        const int k = e - b * KOFF;
        const int t = threadIdx.x;
        const int lid = t & 31;
        const int w = t >> 5;
        __shared__ int wcnt[8];

        int r = b * BM + t;
        int idx = (r < N_ACT) ? nbr[(size_t)k * N_ACT + r] : -1;
        bool valid = (idx >= 0);
        unsigned bal = __ballot_sync(0xFFFFFFFFu, valid);
        if (lid == 0) wcnt[w] = __popc(bal);
        __syncthreads();
        int base = 0;
        #pragma unroll
        for (int j = 0; j < 8; j++) base += (j < w) ? wcnt[j] : 0;
        int pos = base + __popc(bal & ((1u << lid) - 1u));
        if (valid) g_cidx[((size_t)b * KOFF + k) * BM + pos] = idx | (t << 18);
        if (t == 0) {
            int tot = 0;
            #pragma unroll
            for (int j = 0; j < 8; j++) tot += wcnt[j];
            g_cnt[b * KOFF + k] = tot;
        }
    }
}

// ============================================================
// Kernel 2: compacted sparse conv; double-buffered A+B, one barrier/unit
//           (R15 structure verbatim — best measured configuration)
// ============================================================
__global__ void __launch_bounds__(CONV_THREADS, 1)
conv_kernel() {
    extern __shared__ char smem[];
    const uint32_t sb = smem_u32(smem);
    const int tid = threadIdx.x;
    const int wid = tid >> 5;
    const int lid = tid & 31;
    const int b = blockIdx.x;
    const int row0 = b * BM;

    int* s_strip = reinterpret_cast<int*>(smem + OFF_STRIP);   // [2][64]
    int* s_cnt   = reinterpret_cast<int*>(smem + OFF_CNT);
    int* s_work  = reinterpret_cast<int*>(smem + OFF_WORK);
    int* s_nw    = reinterpret_cast<int*>(smem + OFF_NW);

    // ---- zero the smem accumulator (32768 floats) + fetch cnts ----
    {
        float4* a4 = reinterpret_cast<float4*>(smem + OFF_ACC);
        #pragma unroll
        for (int i = 0; i < 16; i++)
            a4[tid + i * CONV_THREADS] = make_float4(0.f, 0.f, 0.f, 0.f);
    }
    if (tid < KOFF) s_cnt[tid] = g_cnt[b * KOFF + tid];
    __syncthreads();
    // worklist entry: (k<<3) | (s<<1) | last_unit_of_k
    if (tid == 0) {
        int nw = 0;
        for (int k = 0; k < KOFF; k++) {
            int ns = (s_cnt[k] + 63) >> 6;
            for (int s = 0; s < ns; s++)
                s_work[nw++] = (k << 3) | (s << 1) | ((s == ns - 1) ? 1 : 0);
        }
        *s_nw = nw;
    }
    __syncthreads();
    const int nwork = *s_nw;

    // ---- tile loaders ----
    auto load_A = [&](int w, int buf) {
        int e = s_work[w];
        int k = e >> 3, s = (e >> 1) & 3;
        int cnt = s_cnt[k];
        int p = tid >> 3;
        int o = tid & 7;
        uint32_t dst0 = sb + OFF_A + (uint32_t)buf * A_TILE + swz(p, o);
        uint32_t dst1 = sb + OFF_A + (uint32_t)buf * A_TILE + swz(p, o + 8);
        int pos = s * 64 + p;
        if (pos < cnt) {
            int ent = __ldg(&g_cidx[((size_t)b * KOFF + k) * BM + pos]);
            if (o == 0) s_strip[buf * 64 + p] = ent;
            const char* src = (const char*)g_Af16 + (size_t)((uint32_t)ent & 0x3FFFFu) * 256 + o * 16;
            cp_async16(dst0, src);
            cp_async16(dst1, src + 128);
        } else {
            sts_fill16(dst0, 0u);
            sts_fill16(dst1, 0u);
        }
    };
    auto load_B = [&](int k, int buf) {
        int n = tid >> 2;
        int qq = tid & 3;
        const char* src = (const char*)g_Wt16 + ((size_t)k * 128 + n) * 256;
        uint32_t base = sb + OFF_B + (uint32_t)buf * B_TILE;
        #pragma unroll
        for (int j = 0; j < 4; j++) {
            int c = qq * 4 + j;
            cp_async16(base + swz(n, c), src + c * 16);
        }
    };

    // ---- per-lane fragment pieces (16 warps: 2M x 8N, warp tile 32x16) ----
    const int mg = wid & 1;
    const int ng = wid >> 1;
    const int a_r0 = mg * 32 + (lid & 15);
    const int a_cs = lid >> 4;                 // A chunk parity
    const int b_r  = ng * 16 + (lid & 7) + ((lid & 16) ? 8 : 0);
    const int b_cs = (lid >> 3) & 1;           // B chunk parity
    const int p_base  = mg * 32 + (lid >> 2);  // compact slot base
    const int pp_base = ng * 8 + (lid & 3);    // acc pair base

    // ---- prime: B(k0) buf0, A(unit 0) buf0 ----
    load_B(s_work[0] >> 3, 0);
    load_A(0, 0);
    cp_commit();
    int bbuf = 0;

    #pragma unroll 1
    for (int w = 0; w < nwork; w++) {
        const int e = s_work[w];
        const int k = e >> 3, s = (e >> 1) & 3;
        const bool last = (e & 1) != 0;
        const int abuf = w & 1;
        const int cnt = s_cnt[k];

        cp_wait<0>();      // A(w) [+B group if pending] complete
        __syncthreads();   // S1: all warps done GEMM(w-1)+scatter(w-1); tiles visible

        // issue next loads (covered by this unit's GEMM + scatter)
        if (w + 1 < nwork) {
            load_A(w + 1, abuf ^ 1);
            if (last) load_B(s_work[w + 1] >> 3, bbuf ^ 1);
            cp_commit();
        }

        // ---- 64x128x128 compact GEMM (warp tile 32x16) ----
        float facc[2][2][4];
        #pragma unroll
        for (int a = 0; a < 2; a++)
            #pragma unroll
            for (int b2 = 0; b2 < 2; b2++)
                #pragma unroll
                for (int c = 0; c < 4; c++) facc[a][b2][c] = 0.f;
        {
            const uint32_t ab  = sb + OFF_A + (uint32_t)abuf * A_TILE;
            const uint32_t bbs = sb + OFF_B + (uint32_t)bbuf * B_TILE;
            #pragma unroll
            for (int ks = 0; ks < 8; ks++) {
                uint32_t af0[4], af1[4], t[4];
                int ca = ks * 2 + a_cs;
                int cb = ks * 2 + b_cs;
                ldsm_x4(af0, ab + swz(a_r0, ca));
                ldsm_x4(af1, ab + swz(a_r0 + 16, ca));
                ldsm_x4(t, bbs + swz(b_r, cb));
                uint32_t bf0[2] = {t[0], t[1]};
                uint32_t bf1[2] = {t[2], t[3]};
                mma16816(facc[0][0], af0, bf0);
                mma16816(facc[0][1], af0, bf1);
                mma16816(facc[1][0], af1, bf0);
                mma16816(facc[1][1], af1, bf1);
            }
        }

        // ---- direct scatter-add into smem accumulator (strip-cached rows) ----
        {
            const int base_s = s * 64;
            #pragma unroll
            for (int mf = 0; mf < 2; mf++)
                #pragma unroll
                for (int h = 0; h < 2; h++) {
                    int slot = p_base + mf * 16 + h * 8;
                    if (base_s + slot < cnt) {
                        int r = ((uint32_t)s_strip[abuf * 64 + slot]) >> 18;
                        #pragma unroll
                        for (int nf = 0; nf < 2; nf++) {
                            uint32_t ad = acc_off(r, pp_base + nf * 4);
                            float2 v = *reinterpret_cast<float2*>(smem + ad);
                            v.x += facc[mf][nf][2 * h];
                            v.y += facc[mf][nf][2 * h + 1];
                            *reinterpret_cast<float2*>(smem + ad) = v;
                        }
                    }
                }
        }
        if (last) bbuf ^= 1;
    }
    __syncthreads();   // final scatter complete

    // ---- epilogue: smem acc -> fp16 intermediate, + BN partials (fp32 stats) ----
    {
        const int pp = tid & 63;     // pair (2 channels)
        const int g  = tid >> 6;     // row group 0..7 (32 rows each)
        float s0 = 0.f, s1 = 0.f, q0 = 0.f, q1 = 0.f;
        #pragma unroll 4
        for (int rr = 0; rr < 32; rr++) {
            int r = g * 32 + rr;
            float2 v = *reinterpret_cast<float2*>(smem + acc_off(r, pp));
            int row = row0 + r;
            if (row < N_ACT)
                reinterpret_cast<__half2*>(g_Cf16)[(size_t)row * 64 + pp] =
                    __floats2half2_rn(v.x, v.y);
            s0 += v.x; s1 += v.y;
            q0 = fmaf(v.x, v.x, q0);
            q1 = fmaf(v.y, v.y, q1);
        }
        __syncthreads();
        float4* red = reinterpret_cast<float4*>(smem + OFF_A);   // [8][64]
        red[g * 64 + pp] = make_float4(s0, s1, q0, q1);
        __syncthreads();
        if (tid < 64) {
            float ts0 = 0.f, ts1 = 0.f, tq0 = 0.f, tq1 = 0.f;
            #pragma unroll
            for (int gg = 0; gg < 8; gg++) {
                float4 v = red[gg * 64 + tid];
                ts0 += v.x; ts1 += v.y; tq0 += v.z; tq1 += v.w;
            }
            g_psum[b * CDIM + tid * 2]     = ts0;
            g_psum[b * CDIM + tid * 2 + 1] = ts1;
            g_psq [b * CDIM + tid * 2]     = tq0;
            g_psq [b * CDIM + tid * 2 + 1] = tq1;
        }
    }
}

// ============================================================
// Kernel 3: finalize BN scale/bias (parallel, deterministic tree)
// ============================================================
__global__ void bn_final_kernel(const float* __restrict__ gamma, const float* __restrict__ beta) {
    __shared__ float ss[256], sq[256];
    int c = blockIdx.x;
    int t = threadIdx.x;
    float s = 0.f, q = 0.f;
    for (int b = t; b < NBLK; b += 256) {
        s += g_psum[b * CDIM + c];
        q += g_psq [b * CDIM + c];
    }
    ss[t] = s; sq[t] = q;
    __syncthreads();
    #pragma unroll
    for (int st = 128; st > 0; st >>= 1) {
        if (t < st) { ss[t] += ss[t + st]; sq[t] += sq[t + st]; }
        __syncthreads();
    }
    if (t == 0) {
        float mean = ss[0] / (float)N_ACT;
        float var  = sq[0] / (float)N_ACT - mean * mean;
        float sc   = gamma[c] * rsqrtf(var + BN_EPS);
        g_scale[c] = sc;
        g_bias[c]  = beta[c] - mean * sc;
    }
}

// ============================================================
// Kernel 4: apply BN + ReLU (reads fp16 intermediate, writes fp32 out)
// ============================================================
__global__ void bn_apply_kernel(float* __restrict__ out) {
    size_t i0 = 2 * ((size_t)blockIdx.x * blockDim.x + threadIdx.x);
    #pragma unroll
    for (int j = 0; j < 2; j++) {
        size_t idx = i0 + j;   // float4-chunk index (4 channels)
        if (idx < (size_t)CVTF_CHUNKS) {
            int c4 = (int)(idx & 31);
            uint2 u = reinterpret_cast<const uint2*>(g_Cf16)[idx];
            float2 v01 = __half22float2(*reinterpret_cast<__half2*>(&u.x));
            float2 v23 = __half22float2(*reinterpret_cast<__half2*>(&u.y));
            float4 sc = reinterpret_cast<float4*>(g_scale)[c4];
            float4 bi = reinterpret_cast<float4*>(g_bias)[c4];
            float4 v;
            v.x = fmaxf(fmaf(v01.x, sc.x, bi.x), 0.f);
            v.y = fmaxf(fmaf(v01.y, sc.y, bi.y), 0.f);
            v.z = fmaxf(fmaf(v23.x, sc.z, bi.z), 0.f);
            v.w = fmaxf(fmaf(v23.y, sc.w, bi.w), 0.f);
            reinterpret_cast<float4*>(out)[idx] = v;
        }
    }
}

// ============================================================
// Launch
// ============================================================
extern "C" void kernel_launch(void* const* d_in, const int* in_sizes, int n_in,
                              void* d_out, int out_size) {
    const float* features = (const float*)d_in[0];
    const int*   nbr      = (const int*)d_in[1];
    const float* W        = (const float*)d_in[2];
    const float* gamma    = (const float*)d_in[3];
    const float* beta     = (const float*)d_in[4];
    float* out = (float*)d_out;

    cudaFuncSetAttribute((const void*)conv_kernel,
                         cudaFuncAttributeMaxDynamicSharedMemorySize, SMEM_TOTAL);

    prep_kernel<<<PREP_BLK, 256>>>(features, W, nbr);
    conv_kernel<<<NBLK, CONV_THREADS, SMEM_TOTAL>>>();
    bn_final_kernel<<<CDIM, 256>>>(gamma, beta);
    bn_apply_kernel<<<(CVTF_CHUNKS / 2 + 255) / 256, 256>>>(out);
}